// round 5
// baseline (speedup 1.0000x reference)
#include <cuda_runtime.h>

// IntensityTransformation: out_k[b,c,h,w] = tf_k[b,c, round(255*img[b,c,h,w])]
// img: [B,C,H,W] f32 (B=8,C=3,H=W=1024), tf1/2/3: [B,C,256] f32.
// Output: concat(out1,out2,out3).
//
// R5: raise occupancy to feed the DRAM pipe.
//  - exact tiling (hw4 = 256 CTAs * 1024 float4): ALL bounds checks removed
//  - __launch_bounds__(256, 6): regcap 42 -> 6 CTAs/SM (48 warps, 75% occ)
//  - keep: 8-way replicated conflict-free LUT, MLP=4 front-batched LDG.128,
//          streaming ld/st hints.

#define ITER 4

__global__ __launch_bounds__(256, 6)
void intensity_lut_kernel(const float4* __restrict__ img,
                          const float*  __restrict__ tf1,
                          const float*  __restrict__ tf2,
                          const float*  __restrict__ tf3,
                          float4* __restrict__ out,
                          int hw4,     // H*W/4 per (b,c) plane (exact multiple of 1024)
                          int tot4)    // B*C*H*W/4 (stride between outputs)
{
    __shared__ float4 lut[256 * 8];   // 32 KB: 8 replicas, interleaved per-entry

    const int bc  = blockIdx.y;
    const int t   = threadIdx.x;
    const int rep = t & 7;

    // Fill: thread t owns replica (t&7), entries e = (t>>3) + 32*j.
    // STS bank = rep*4 per phase: conflict-free.
    {
        const int e0    = t >> 3;            // 0..31
        const int lbase = bc * 256;
#pragma unroll
        for (int j = 0; j < 8; j++) {
            const int e = e0 + j * 32;
            const int g = lbase + e;
            lut[(e << 3) | rep] = make_float4(tf1[g], tf2[g], tf3[g], 0.0f);
        }
    }
    __syncthreads();

    const int base = bc * hw4 + blockIdx.x * (256 * ITER) + t;

    const float4* __restrict__ src  = img + base;
    float4* __restrict__ dst0 = out + base;
    float4* __restrict__ dst1 = dst0 + tot4;
    float4* __restrict__ dst2 = dst1 + tot4;

    // Front-batched loads: 4 independent LDG.128 in flight (MLP=4). No tail.
    float4 v[ITER];
#pragma unroll
    for (int k = 0; k < ITER; k++)
        v[k] = __ldcs(&src[k * 256]);

#pragma unroll
    for (int k = 0; k < ITER; k++) {
        // idx in [0,255] guaranteed (img uniform in [0,1)).
        const int i0 = __float2int_rn(255.0f * v[k].x);
        const int i1 = __float2int_rn(255.0f * v[k].y);
        const int i2 = __float2int_rn(255.0f * v[k].z);
        const int i3 = __float2int_rn(255.0f * v[k].w);

        const float4 l0 = lut[(i0 << 3) | rep];
        const float4 l1 = lut[(i1 << 3) | rep];
        const float4 l2 = lut[(i2 << 3) | rep];
        const float4 l3 = lut[(i3 << 3) | rep];

        __stcs(&dst0[k * 256], make_float4(l0.x, l1.x, l2.x, l3.x));
        __stcs(&dst1[k * 256], make_float4(l0.y, l1.y, l2.y, l3.y));
        __stcs(&dst2[k * 256], make_float4(l0.z, l1.z, l2.z, l3.z));
    }
}

extern "C" void kernel_launch(void* const* d_in, const int* in_sizes, int n_in,
                              void* d_out, int out_size) {
    const float* img = (const float*)d_in[0];
    const float* tf1 = (const float*)d_in[1];
    const float* tf2 = (const float*)d_in[2];
    const float* tf3 = (const float*)d_in[3];
    float* out = (float*)d_out;

    const int n_img  = in_sizes[0];          // B*C*H*W
    const int n_lut  = in_sizes[1];          // B*C*256
    const int BC     = n_lut / 256;          // 24
    const int HW     = n_img / BC;           // 1048576
    const int hw4    = HW / 4;               // 262144  (= 256 * 1024 exactly)
    const int tot4   = n_img / 4;            // 6291456

    dim3 block(256);
    const int per_cta = 256 * ITER;          // 1024
    dim3 grid(hw4 / per_cta, BC);            // (256, 24) — exact, no tail
    intensity_lut_kernel<<<grid, block>>>(
        (const float4*)img, tf1, tf2, tf3, (float4*)out, hw4, tot4);
}

// round 6
// speedup vs baseline: 1.1172x; 1.1172x over previous
#include <cuda_runtime.h>

// IntensityTransformation: out_k[b,c,h,w] = tf_k[b,c, round(255*img[b,c,h,w])]
// img: [B,C,H,W] f32 (B=8,C=3,H=W=1024), tf1/2/3: [B,C,256] f32.
// Output: concat(out1,out2,out3).
//
// R6: FEWER, LONGER streams. R5 showed DRAM% falls as resident CTAs rise
// (stream-count thrash). ITER=8, natural regs (~64) -> 4 CTAs/SM, each CTA
// covers 32KB per output stream. Keep: 8-way replicated conflict-free LUT,
// front-batched LDG.128 (MLP=8), exact no-tail tiling, streaming hints.

#define ITER 8

__global__ __launch_bounds__(256)
void intensity_lut_kernel(const float4* __restrict__ img,
                          const float*  __restrict__ tf1,
                          const float*  __restrict__ tf2,
                          const float*  __restrict__ tf3,
                          float4* __restrict__ out,
                          int hw4,     // H*W/4 per (b,c) plane (exact multiple of 2048)
                          int tot4)    // B*C*H*W/4 (stride between outputs)
{
    __shared__ float4 lut[256 * 8];   // 32 KB: 8 replicas, interleaved per-entry

    const int bc  = blockIdx.y;
    const int t   = threadIdx.x;
    const int rep = t & 7;

    // Fill: thread t owns replica (t&7), entries e = (t>>3) + 32*j.
    // STS bank = rep*4 per phase: conflict-free.
    {
        const int e0    = t >> 3;            // 0..31
        const int lbase = bc * 256;
#pragma unroll
        for (int j = 0; j < 8; j++) {
            const int e = e0 + j * 32;
            const int g = lbase + e;
            lut[(e << 3) | rep] = make_float4(tf1[g], tf2[g], tf3[g], 0.0f);
        }
    }
    __syncthreads();

    const int base = bc * hw4 + blockIdx.x * (256 * ITER) + t;

    const float4* __restrict__ src  = img + base;
    float4* __restrict__ dst0 = out + base;
    float4* __restrict__ dst1 = dst0 + tot4;
    float4* __restrict__ dst2 = dst1 + tot4;

    // Front-batched loads: 8 independent LDG.128 in flight per thread. No tail.
    float4 v[ITER];
#pragma unroll
    for (int k = 0; k < ITER; k++)
        v[k] = __ldcs(&src[k * 256]);

#pragma unroll
    for (int k = 0; k < ITER; k++) {
        // idx in [0,255] guaranteed (img uniform in [0,1)).
        const int i0 = __float2int_rn(255.0f * v[k].x);
        const int i1 = __float2int_rn(255.0f * v[k].y);
        const int i2 = __float2int_rn(255.0f * v[k].z);
        const int i3 = __float2int_rn(255.0f * v[k].w);

        const float4 l0 = lut[(i0 << 3) | rep];
        const float4 l1 = lut[(i1 << 3) | rep];
        const float4 l2 = lut[(i2 << 3) | rep];
        const float4 l3 = lut[(i3 << 3) | rep];

        __stcs(&dst0[k * 256], make_float4(l0.x, l1.x, l2.x, l3.x));
        __stcs(&dst1[k * 256], make_float4(l0.y, l1.y, l2.y, l3.y));
        __stcs(&dst2[k * 256], make_float4(l0.z, l1.z, l2.z, l3.z));
    }
}

extern "C" void kernel_launch(void* const* d_in, const int* in_sizes, int n_in,
                              void* d_out, int out_size) {
    const float* img = (const float*)d_in[0];
    const float* tf1 = (const float*)d_in[1];
    const float* tf2 = (const float*)d_in[2];
    const float* tf3 = (const float*)d_in[3];
    float* out = (float*)d_out;

    const int n_img  = in_sizes[0];          // B*C*H*W
    const int n_lut  = in_sizes[1];          // B*C*256
    const int BC     = n_lut / 256;          // 24
    const int HW     = n_img / BC;           // 1048576
    const int hw4    = HW / 4;               // 262144 (= 128 * 2048 exactly)
    const int tot4   = n_img / 4;            // 6291456

    dim3 block(256);
    const int per_cta = 256 * ITER;          // 2048
    dim3 grid(hw4 / per_cta, BC);            // (128, 24) — exact, no tail
    intensity_lut_kernel<<<grid, block>>>(
        (const float4*)img, tf1, tf2, tf3, (float4*)out, hw4, tot4);
}

// round 7
// speedup vs baseline: 1.1254x; 1.0073x over previous
#include <cuda_runtime.h>

// IntensityTransformation: out_k[b,c,h,w] = tf_k[b,c, round(255*img[b,c,h,w])]
// img: [B,C,H,W] f32 (B=8,C=3,H=W=1024), tf1/2/3: [B,C,256] f32.
// Output: concat(out1,out2,out3).
//
// R7: store-stream BURSTING for DRAM row-buffer locality. Compute all
// ITER x 3 output quads into registers first, then issue all stores to
// out1 back-to-back, then out2, then out3 (2KB/warp same-stream bursts
// instead of 512B interleaved across 3 streams). Keep: replicated
// conflict-free LUT, MLP=4 front-batched loads, exact tiling, streaming hints.

#define ITER 4

__global__ __launch_bounds__(256)
void intensity_lut_kernel(const float4* __restrict__ img,
                          const float*  __restrict__ tf1,
                          const float*  __restrict__ tf2,
                          const float*  __restrict__ tf3,
                          float4* __restrict__ out,
                          int hw4,     // H*W/4 per (b,c) plane (exact multiple of 1024)
                          int tot4)    // B*C*H*W/4 (stride between outputs)
{
    __shared__ float4 lut[256 * 8];   // 32 KB: 8 replicas, interleaved per-entry

    const int bc  = blockIdx.y;
    const int t   = threadIdx.x;
    const int rep = t & 7;

    // Fill: thread t owns replica (t&7), entries e = (t>>3) + 32*j.
    // STS bank = rep*4 per phase: conflict-free.
    {
        const int e0    = t >> 3;            // 0..31
        const int lbase = bc * 256;
#pragma unroll
        for (int j = 0; j < 8; j++) {
            const int e = e0 + j * 32;
            const int g = lbase + e;
            lut[(e << 3) | rep] = make_float4(tf1[g], tf2[g], tf3[g], 0.0f);
        }
    }
    __syncthreads();

    const int base = bc * hw4 + blockIdx.x * (256 * ITER) + t;

    const float4* __restrict__ src  = img + base;
    float4* __restrict__ dst0 = out + base;
    float4* __restrict__ dst1 = dst0 + tot4;
    float4* __restrict__ dst2 = dst1 + tot4;

    // Phase 1: front-batched loads (MLP=4). No tail (exact tiling).
    float4 v[ITER];
#pragma unroll
    for (int k = 0; k < ITER; k++)
        v[k] = __ldcs(&src[k * 256]);

    // Phase 2: all gathers -> registers (r0/r1/r2 = out1/out2/out3 quads).
    float4 r0[ITER], r1[ITER], r2[ITER];
#pragma unroll
    for (int k = 0; k < ITER; k++) {
        // idx in [0,255] guaranteed (img uniform in [0,1)).
        const int i0 = __float2int_rn(255.0f * v[k].x);
        const int i1 = __float2int_rn(255.0f * v[k].y);
        const int i2 = __float2int_rn(255.0f * v[k].z);
        const int i3 = __float2int_rn(255.0f * v[k].w);

        const float4 l0 = lut[(i0 << 3) | rep];
        const float4 l1 = lut[(i1 << 3) | rep];
        const float4 l2 = lut[(i2 << 3) | rep];
        const float4 l3 = lut[(i3 << 3) | rep];

        r0[k] = make_float4(l0.x, l1.x, l2.x, l3.x);
        r1[k] = make_float4(l0.y, l1.y, l2.y, l3.y);
        r2[k] = make_float4(l0.z, l1.z, l2.z, l3.z);
    }

    // Phase 3: per-stream store bursts (long same-page runs per channel).
#pragma unroll
    for (int k = 0; k < ITER; k++)
        __stcs(&dst0[k * 256], r0[k]);
#pragma unroll
    for (int k = 0; k < ITER; k++)
        __stcs(&dst1[k * 256], r1[k]);
#pragma unroll
    for (int k = 0; k < ITER; k++)
        __stcs(&dst2[k * 256], r2[k]);
}

extern "C" void kernel_launch(void* const* d_in, const int* in_sizes, int n_in,
                              void* d_out, int out_size) {
    const float* img = (const float*)d_in[0];
    const float* tf1 = (const float*)d_in[1];
    const float* tf2 = (const float*)d_in[2];
    const float* tf3 = (const float*)d_in[3];
    float* out = (float*)d_out;

    const int n_img  = in_sizes[0];          // B*C*H*W
    const int n_lut  = in_sizes[1];          // B*C*256
    const int BC     = n_lut / 256;          // 24
    const int HW     = n_img / BC;           // 1048576
    const int hw4    = HW / 4;               // 262144 (= 256 * 1024 exactly)
    const int tot4   = n_img / 4;            // 6291456

    dim3 block(256);
    const int per_cta = 256 * ITER;          // 1024
    dim3 grid(hw4 / per_cta, BC);            // (256, 24) — exact, no tail
    intensity_lut_kernel<<<grid, block>>>(
        (const float4*)img, tf1, tf2, tf3, (float4*)out, hw4, tot4);
}